// round 16
// baseline (speedup 1.0000x reference)
#include <cuda_runtime.h>

// Problem constants (fixed shapes for this problem)
#define T_STEPS 4096
#define BATCH   256
#define CHUNK   128   // x prefetch chunk (steps); CHUNK*8 floats per buffer

typedef unsigned long long ull;

// ---- packed f32x2 helpers (SASS FFMA2 path, PTX-only) ----
__device__ __forceinline__ ull pack2(float lo, float hi) {
    ull r; asm("mov.b64 %0, {%1, %2};" : "=l"(r) : "f"(lo), "f"(hi)); return r;
}
__device__ __forceinline__ void unpack2(ull v, float& lo, float& hi) {
    asm("mov.b64 {%0, %1}, %2;" : "=f"(lo), "=f"(hi) : "l"(v));
}
__device__ __forceinline__ ull fma2(ull a, ull b, ull c) {
    ull d; asm("fma.rn.f32x2 %0, %1, %2, %3;" : "=l"(d) : "l"(a), "l"(b), "l"(c)); return d;
}
__device__ __forceinline__ float hsum4(ull a, ull b) {
    float ax, ay, bx, by; unpack2(a, ax, ay); unpack2(b, bx, by);
    return (ax + ay) + (bx + by);
}

// ---- fast-but-accurate activations (MUFU ex2 + rcp, ~2 ulp) ----
__device__ __forceinline__ float rcp_fast(float x) {
    float r; asm("rcp.approx.f32 %0, %1;" : "=f"(r) : "f"(x)); return r;
}
__device__ __forceinline__ float sigmoid_f(float x) {
    return rcp_fast(1.0f + __expf(-x));
}
__device__ __forceinline__ float tanh_f(float x) {
    // tanh(x) = 1 - 2/(e^{2x}+1); exact limits at +/-inf via rcp(inf)=0
    return fmaf(-2.0f, rcp_fast(__expf(2.0f * x) + 1.0f), 1.0f);
}

__global__ void __launch_bounds__(128, 2) lstm_seq_kernel(
    const float* __restrict__ x,
    const float* __restrict__ W_ih1, const float* __restrict__ W_hh1,
    const float* __restrict__ b_ih1, const float* __restrict__ b_hh1,
    const float* __restrict__ W_ih2, const float* __restrict__ W_hh2,
    const float* __restrict__ b_ih2, const float* __restrict__ b_hh2,
    const float* __restrict__ W_lin, const float* __restrict__ b_lin,
    float* __restrict__ out)
{
    const int b    = blockIdx.x;     // one CTA per batch element
    const int j    = threadIdx.x;    // gate index 0..127 (i:0-31 f:32-63 g:64-95 o:96-127)
    const int gtyp = j >> 5;
    const int hid  = j & 31;

    __shared__ __align__(16) float xs[2][CHUNK * 8];  // double-buffered input
    __shared__ __align__(16) float h1s[32];
    __shared__ __align__(16) float h2s[32];
    __shared__ __align__(16) float g1sf[128];         // activated gates, [hid][gate]
    __shared__ __align__(16) float g2sf[128];

    // ---- load all weights into registers once (reused 4096x) ----
    // K-paired as 64-bit packed (lo = even k, hi = odd k). Rows are 8B-aligned.
    ull wx1[4], wh1[16], wa2[16], wb2[16], wl[16];
    {
        const ull* p = (const ull*)(W_ih1 + j * 8);
        #pragma unroll
        for (int k = 0; k < 4; k++) wx1[k] = p[k];
        p = (const ull*)(W_hh1 + j * 32);
        #pragma unroll
        for (int k = 0; k < 16; k++) wh1[k] = p[k];
        p = (const ull*)(W_ih2 + j * 32);
        #pragma unroll
        for (int k = 0; k < 16; k++) wa2[k] = p[k];
        p = (const ull*)(W_hh2 + j * 32);
        #pragma unroll
        for (int k = 0; k < 16; k++) wb2[k] = p[k];
        const int jl = (j < 80) ? j : 0;               // clamp to stay in-bounds
        p = (const ull*)(W_lin + jl * 32);
        #pragma unroll
        for (int k = 0; k < 16; k++) wl[k] = p[k];
    }
    const float bias1 = b_ih1[j] + b_hh1[j];
    const float bias2 = b_ih2[j] + b_hh2[j];
    const float blin  = (j < 80) ? b_lin[j] : 0.0f;

    if (j < 32) { h1s[j] = 0.0f; h2s[j] = 0.0f; }
    float c1 = 0.0f;   // owned by threads 0..31  (hidden unit = j)
    float c2 = 0.0f;   // owned by threads 32..63 (hidden unit = j&31)

    const float* xg = x   + (size_t)b * (T_STEPS * 8);
    float*       og = out + (size_t)b * (T_STEPS * 80);

    // preload chunk 0: 1024 floats = 128 threads x 2 float4
    {
        const float4* src = (const float4*)xg;
        float4* dst = (float4*)xs[0];
        dst[2 * j] = src[2 * j];
        dst[2 * j + 1] = src[2 * j + 1];
    }
    __syncthreads();

    for (int t0 = 0; t0 < T_STEPS; t0 += CHUNK) {
        const int  buf = (t0 / CHUNK) & 1;
        const bool has = (t0 + CHUNK) < T_STEPS;
        float4 va, vb;
        if (has) {  // prefetch next chunk into registers (overlaps compute)
            const float4* src = (const float4*)(xg + (size_t)(t0 + CHUNK) * 8);
            va = src[2 * j];
            vb = src[2 * j + 1];
        }

        #pragma unroll 1
        for (int tt = 0; tt < CHUNK; ++tt) {
            const ull* xq = (const ull*)(&xs[buf][tt * 8]);

            // ---- phase A (depends only on previous step): gates1 full ----
            ull a0 = pack2(bias1, 0.0f), a1 = 0ull;
            a0 = fma2(wx1[0], xq[0], a0);
            a1 = fma2(wx1[1], xq[1], a1);
            a0 = fma2(wx1[2], xq[2], a0);
            a1 = fma2(wx1[3], xq[3], a1);
            const ull* h1q = (const ull*)h1s;
            #pragma unroll
            for (int k = 0; k < 16; k += 2) {
                a0 = fma2(wh1[k],     h1q[k],     a0);
                a1 = fma2(wh1[k + 1], h1q[k + 1], a1);
            }
            // ---- gates2 partial: W_hh2 @ h2_prev (off critical path) ----
            ull b0 = pack2(bias2, 0.0f), b1 = 0ull;
            const ull* h2q = (const ull*)h2s;
            #pragma unroll
            for (int k = 0; k < 16; k += 2) {
                b0 = fma2(wb2[k],     h2q[k],     b0);
                b1 = fma2(wb2[k + 1], h2q[k + 1], b1);
            }

            const float pre1 = hsum4(a0, a1);
            const float act1 = (gtyp == 2) ? tanh_f(pre1) : sigmoid_f(pre1);
            g1sf[hid * 4 + gtyp] = act1;
            __syncthreads();                       // bar1: gates1 ready

            if (j < 32) {                          // layer-1 cell update
                const float4 ga = ((const float4*)g1sf)[j];   // (i,f,g,o)
                c1 = fmaf(ga.y, c1, ga.x * ga.z);
                h1s[j] = ga.w * tanh_f(c1);
            }
            __syncthreads();                       // bar2: h1 ready

            // ---- gates2 finish: W_ih2 @ h1_new ----
            const ull* h1n = (const ull*)h1s;
            #pragma unroll
            for (int k = 0; k < 16; k += 2) {
                b0 = fma2(wa2[k],     h1n[k],     b0);
                b1 = fma2(wa2[k + 1], h1n[k + 1], b1);
            }
            const float pre2 = hsum4(b0, b1);
            const float act2 = (gtyp == 2) ? tanh_f(pre2) : sigmoid_f(pre2);
            g2sf[hid * 4 + gtyp] = act2;
            __syncthreads();                       // bar3: gates2 ready

            if (j >= 32 && j < 64) {               // layer-2 cell update
                const float4 ga = ((const float4*)g2sf)[hid];
                c2 = fmaf(ga.y, c2, ga.x * ga.z);
                h2s[hid] = ga.w * tanh_f(c2);
            }
            __syncthreads();                       // bar4: h2 ready

            // ---- linear head (overlaps next step's phase A) ----
            if (j < 80) {
                ull o0 = pack2(blin, 0.0f), o1 = 0ull;
                const ull* h2n = (const ull*)h2s;
                #pragma unroll
                for (int k = 0; k < 16; k += 2) {
                    o0 = fma2(wl[k],     h2n[k],     o0);
                    o1 = fma2(wl[k + 1], h2n[k + 1], o1);
                }
                og[(size_t)(t0 + tt) * 80 + j] = hsum4(o0, o1);
            }
        }

        if (has) {  // commit prefetched chunk to the other buffer
            float4* dst = (float4*)xs[buf ^ 1];
            dst[2 * j] = va;
            dst[2 * j + 1] = vb;
        }
        __syncthreads();
    }
}

extern "C" void kernel_launch(void* const* d_in, const int* in_sizes, int n_in,
                              void* d_out, int out_size) {
    const float* x     = (const float*)d_in[0];
    const float* W_ih1 = (const float*)d_in[1];
    const float* W_hh1 = (const float*)d_in[2];
    const float* b_ih1 = (const float*)d_in[3];
    const float* b_hh1 = (const float*)d_in[4];
    const float* W_ih2 = (const float*)d_in[5];
    const float* W_hh2 = (const float*)d_in[6];
    const float* b_ih2 = (const float*)d_in[7];
    const float* b_hh2 = (const float*)d_in[8];
    const float* W_lin = (const float*)d_in[9];
    const float* b_lin = (const float*)d_in[10];
    float* out = (float*)d_out;

    lstm_seq_kernel<<<BATCH, 128>>>(x, W_ih1, W_hh1, b_ih1, b_hh1,
                                    W_ih2, W_hh2, b_ih2, b_hh2,
                                    W_lin, b_lin, out);
}

// round 17
// speedup vs baseline: 1.2843x; 1.2843x over previous
#include <cuda_runtime.h>

// Problem constants (fixed shapes for this problem)
#define T_STEPS 4096
#define BATCH   256
#define CHUNK   128   // x prefetch chunk (steps); CHUNK*8 floats per buffer

typedef unsigned long long ull;

// ---- packed f32x2 helpers (SASS FFMA2 path, PTX-only) ----
__device__ __forceinline__ ull pack2(float lo, float hi) {
    ull r; asm("mov.b64 %0, {%1, %2};" : "=l"(r) : "f"(lo), "f"(hi)); return r;
}
__device__ __forceinline__ void unpack2(ull v, float& lo, float& hi) {
    asm("mov.b64 {%0, %1}, %2;" : "=f"(lo), "=f"(hi) : "l"(v));
}
__device__ __forceinline__ ull fma2(ull a, ull b, ull c) {
    ull d; asm("fma.rn.f32x2 %0, %1, %2, %3;" : "=l"(d) : "l"(a), "l"(b), "l"(c)); return d;
}
__device__ __forceinline__ float hsum4(ull a, ull b) {
    float ax, ay, bx, by; unpack2(a, ax, ay); unpack2(b, bx, by);
    return (ax + ay) + (bx + by);
}

// ---- fast-but-accurate activations (MUFU ex2 + rcp, ~2 ulp) ----
__device__ __forceinline__ float rcp_fast(float x) {
    float r; asm("rcp.approx.f32 %0, %1;" : "=f"(r) : "f"(x)); return r;
}
__device__ __forceinline__ float ex2_fast(float x) {
    float r; asm("ex2.approx.f32 %0, %1;" : "=f"(r) : "f"(x)); return r;
}
// tanh(x) = 1 - 2/(e^{2x}+1); exact limits at +/-inf via rcp(inf)=0
__device__ __forceinline__ float tanh_f(float x) {
    return fmaf(-2.0f, rcp_fast(ex2_fast(2.8853900817779268f * x) + 1.0f), 1.0f);
}

__global__ void __launch_bounds__(128, 2) lstm_seq_kernel(
    const float* __restrict__ x,
    const float* __restrict__ W_ih1, const float* __restrict__ W_hh1,
    const float* __restrict__ b_ih1, const float* __restrict__ b_hh1,
    const float* __restrict__ W_ih2, const float* __restrict__ W_hh2,
    const float* __restrict__ b_ih2, const float* __restrict__ b_hh2,
    const float* __restrict__ W_lin, const float* __restrict__ b_lin,
    float* __restrict__ out)
{
    const int b  = blockIdx.x;      // one CTA per batch element
    const int j  = threadIdx.x;     // 128 threads
    const int u  = j >> 2;          // hidden unit 0..31 (quad index)
    const int g  = j & 3;           // gate: 0=i, 1=f, 2=g(tanh), 3=o
    const int r  = g * 32 + u;      // weight row in torch gate order
    const int qb = (j & 31) & ~3;   // quad base lane within warp

    __shared__ __align__(16) float xs[2][CHUNK * 8];  // double-buffered input
    __shared__ __align__(8)  float h1s[2][32];        // double-buffered h1
    __shared__ __align__(8)  float h2s[2][32];        // double-buffered h2

    // ---- load all weights into registers once (reused 4096x) ----
    // K-paired as 64-bit packed (lo = even k, hi = odd k). Rows are 8B-aligned.
    ull wx1[4], wh1[16], wa2[16], wb2[16], wl[16];
    {
        const ull* p = (const ull*)(W_ih1 + r * 8);
        #pragma unroll
        for (int k = 0; k < 4; k++) wx1[k] = p[k];
        p = (const ull*)(W_hh1 + r * 32);
        #pragma unroll
        for (int k = 0; k < 16; k++) wh1[k] = p[k];
        p = (const ull*)(W_ih2 + r * 32);
        #pragma unroll
        for (int k = 0; k < 16; k++) wa2[k] = p[k];
        p = (const ull*)(W_hh2 + r * 32);
        #pragma unroll
        for (int k = 0; k < 16; k++) wb2[k] = p[k];
        const int jl = (j < 80) ? j : 0;               // clamp to stay in-bounds
        p = (const ull*)(W_lin + jl * 32);
        #pragma unroll
        for (int k = 0; k < 16; k++) wl[k] = p[k];
    }
    const float bias1 = b_ih1[r] + b_hh1[r];
    const float bias2 = b_ih2[r] + b_hh2[r];
    const float blin  = (j < 80) ? b_lin[j] : 0.0f;

    // Branchless activation params: act(x) = s0 + s1 * rcp(1 + ex2(a2*x))
    //   sigmoid: a2 = -log2e,  s1 = 1,  s0 = 0
    //   tanh:    a2 = 2*log2e, s1 = -2, s0 = 1
    const float LGE = 1.4426950408889634f;
    const float a2c = (g == 2) ?  2.0f * LGE : -LGE;
    const float s1c = (g == 2) ? -2.0f : 1.0f;
    const float s0c = (g == 2) ?  1.0f : 0.0f;

    if (j < 32) { h1s[0][j] = 0.0f; h2s[0][j] = 0.0f; }
    float c1 = 0.0f;   // cell state of unit u (replicated across the quad)
    float c2 = 0.0f;

    const float* xg = x   + (size_t)b * (T_STEPS * 8);
    float*       og = out + (size_t)b * (T_STEPS * 80);

    // preload chunk 0: 1024 floats = 128 threads x 2 float4
    {
        const float4* src = (const float4*)xg;
        float4* dst = (float4*)xs[0];
        dst[2 * j] = src[2 * j];
        dst[2 * j + 1] = src[2 * j + 1];
    }
    __syncthreads();

    int p = 0;  // h double-buffer parity

    for (int t0 = 0; t0 < T_STEPS; t0 += CHUNK) {
        const int  buf = (t0 / CHUNK) & 1;
        const bool has = (t0 + CHUNK) < T_STEPS;
        float4 va, vb;
        if (has) {  // prefetch next chunk into registers (overlaps compute)
            const float4* src = (const float4*)(xg + (size_t)(t0 + CHUNK) * 8);
            va = src[2 * j];
            vb = src[2 * j + 1];
        }

        #pragma unroll 2
        for (int tt = 0; tt < CHUNK; ++tt) {
            const ull* xq  = (const ull*)(&xs[buf][tt * 8]);
            const ull* h1q = (const ull*)h1s[p];
            const ull* h2q = (const ull*)h2s[p];

            // ---- phase A: gates1 full + gates2 hh-part (4 indep chains) ----
            ull a0 = pack2(bias1, 0.0f), a1 = 0ull;
            ull b0 = pack2(bias2, 0.0f), b1 = 0ull;
            a0 = fma2(wx1[0], xq[0], a0);
            a1 = fma2(wx1[1], xq[1], a1);
            a0 = fma2(wx1[2], xq[2], a0);
            a1 = fma2(wx1[3], xq[3], a1);
            #pragma unroll
            for (int k = 0; k < 16; k += 2) {
                a0 = fma2(wh1[k],     h1q[k],     a0);
                a1 = fma2(wh1[k + 1], h1q[k + 1], a1);
                b0 = fma2(wb2[k],     h2q[k],     b0);
                b1 = fma2(wb2[k + 1], h2q[k + 1], b1);
            }

            const float pre1 = hsum4(a0, a1);
            const float act1 = fmaf(s1c, rcp_fast(1.0f + ex2_fast(a2c * pre1)), s0c);

            // quad gather (i,f,g,o of unit u are in lanes qb..qb+3)
            const float i1 = __shfl_sync(0xffffffffu, act1, qb + 0);
            const float f1 = __shfl_sync(0xffffffffu, act1, qb + 1);
            const float g1 = __shfl_sync(0xffffffffu, act1, qb + 2);
            const float o1 = __shfl_sync(0xffffffffu, act1, qb + 3);
            c1 = fmaf(f1, c1, i1 * g1);
            const float h1v = o1 * tanh_f(c1);
            if (g == 0) h1s[p ^ 1][u] = h1v;
            __syncthreads();                       // bar1: h1 ready

            // ---- phase B: gates2 ih-part on new h1 ----
            const ull* h1n = (const ull*)h1s[p ^ 1];
            #pragma unroll
            for (int k = 0; k < 16; k += 2) {
                b0 = fma2(wa2[k],     h1n[k],     b0);
                b1 = fma2(wa2[k + 1], h1n[k + 1], b1);
            }
            const float pre2 = hsum4(b0, b1);
            const float act2 = fmaf(s1c, rcp_fast(1.0f + ex2_fast(a2c * pre2)), s0c);

            const float i2 = __shfl_sync(0xffffffffu, act2, qb + 0);
            const float f2 = __shfl_sync(0xffffffffu, act2, qb + 1);
            const float g2 = __shfl_sync(0xffffffffu, act2, qb + 2);
            const float o2 = __shfl_sync(0xffffffffu, act2, qb + 3);
            c2 = fmaf(f2, c2, i2 * g2);
            const float h2v = o2 * tanh_f(c2);
            if (g == 0) h2s[p ^ 1][u] = h2v;
            __syncthreads();                       // bar2: h2 ready

            // ---- linear head (overlaps next step's phase A) ----
            if (j < 80) {
                ull o0 = pack2(blin, 0.0f), o1r = 0ull;
                const ull* h2n = (const ull*)h2s[p ^ 1];
                #pragma unroll
                for (int k = 0; k < 16; k += 2) {
                    o0  = fma2(wl[k],     h2n[k],     o0);
                    o1r = fma2(wl[k + 1], h2n[k + 1], o1r);
                }
                og[(size_t)(t0 + tt) * 80 + j] = hsum4(o0, o1r);
            }

            p ^= 1;
        }

        if (has) {  // commit prefetched chunk to the other buffer
            float4* dst = (float4*)xs[buf ^ 1];
            dst[2 * j] = va;
            dst[2 * j + 1] = vb;
        }
        __syncthreads();
    }
}

extern "C" void kernel_launch(void* const* d_in, const int* in_sizes, int n_in,
                              void* d_out, int out_size) {
    const float* x     = (const float*)d_in[0];
    const float* W_ih1 = (const float*)d_in[1];
    const float* W_hh1 = (const float*)d_in[2];
    const float* b_ih1 = (const float*)d_in[3];
    const float* b_hh1 = (const float*)d_in[4];
    const float* W_ih2 = (const float*)d_in[5];
    const float* W_hh2 = (const float*)d_in[6];
    const float* b_ih2 = (const float*)d_in[7];
    const float* b_hh2 = (const float*)d_in[8];
    const float* W_lin = (const float*)d_in[9];
    const float* b_lin = (const float*)d_in[10];
    float* out = (float*)d_out;

    lstm_seq_kernel<<<BATCH, 128>>>(x, W_ih1, W_hh1, b_ih1, b_hh1,
                                    W_ih2, W_hh2, b_ih2, b_hh2,
                                    W_lin, b_lin, out);
}